// round 13
// baseline (speedup 1.0000x reference)
#include <cuda_runtime.h>
#include <cuda_fp16.h>
#include <cstdint>
#include <cstddef>

#define MDIM 16384
#define NDIM 4096
#define KDIM 2048
#define HDIM 1024

#define BM 128
#define BN 128
#define BK 64
#define STAGES 3
#define THREADS 128
#define NKT (KDIM / BK)              // 32
#define NT_TILES 4096                // (NDIM/BN) * (MDIM/BM)

#define A_BYTES 16384
#define B_BYTES 16384
#define STAGE_BYTES (A_BYTES + B_BYTES)   // 32768

// Fragment-packed operands (device globals: allowed scratch)
__device__ __half g_Apack[(size_t)MDIM * KDIM];   // 64 MB
__device__ __half g_Wpack[(size_t)NDIM * KDIM];   // 16 MB

// ---------------- helpers ----------------
__device__ __forceinline__ uint32_t cvta_s(const void* p) {
    return (uint32_t)__cvta_generic_to_shared(p);
}
__device__ __forceinline__ void cp_async16(uint32_t s, const void* g) {
    asm volatile("cp.async.cg.shared.global [%0], [%1], 16;\n" :: "r"(s), "l"(g));
}
__device__ __forceinline__ void cp_commit() { asm volatile("cp.async.commit_group;\n" ::: "memory"); }
#define CP_WAIT(n) asm volatile("cp.async.wait_group %0;\n" :: "n"(n) : "memory")

__device__ __forceinline__ void mma_f16(float* d, const uint32_t* a, const uint32_t* b) {
    asm volatile("mma.sync.aligned.m16n8k16.row.col.f32.f16.f16.f32 "
        "{%0,%1,%2,%3}, {%4,%5,%6,%7}, {%8,%9}, {%0,%1,%2,%3};\n"
        : "+f"(d[0]), "+f"(d[1]), "+f"(d[2]), "+f"(d[3])
        : "r"(a[0]), "r"(a[1]), "r"(a[2]), "r"(a[3]), "r"(b[0]), "r"(b[1]));
}
__device__ __forceinline__ float tanh_fast(float x) {
    float r; asm("tanh.approx.f32 %0, %1;\n" : "=f"(r) : "f"(x)); return r;
}
__device__ __forceinline__ float sigmoid_fast(float x) {
    return fmaf(tanh_fast(0.5f * x), 0.5f, 0.5f);
}

// ---------------- merged pack kernel (verified round 7) ----------------
__global__ void pack_AW(const float* __restrict__ inc, const float* __restrict__ oh,
                        const float* __restrict__ Wi, const float* __restrict__ Wh,
                        int aBlocks) {
    if ((int)blockIdx.x < aBlocks) {
        int idx = blockIdx.x * blockDim.x + threadIdx.x;
        int lane = idx & 31;
        int unit = idx >> 5;
        int kblk = unit & 127;
        int mblk = unit >> 7;
        int gid = lane >> 2, q = lane & 3;
        int m0 = mblk * 16 + gid;
        int k0 = kblk * 16 + 2 * q;
        const float* src;
        if (k0 < 1024) src = inc + (size_t)m0 * 1024 + k0;
        else           src = oh  + (size_t)m0 * 1024 + (k0 - 1024);
        float2 v0 = *(const float2*)(src);
        float2 v1 = *(const float2*)(src + 8 * 1024);
        float2 v2 = *(const float2*)(src + 8);
        float2 v3 = *(const float2*)(src + 8 * 1024 + 8);
        __half2 h[4];
        h[0] = __floats2half2_rn(v0.x, v0.y);
        h[1] = __floats2half2_rn(v1.x, v1.y);
        h[2] = __floats2half2_rn(v2.x, v2.y);
        h[3] = __floats2half2_rn(v3.x, v3.y);
        *(float4*)(g_Apack + (size_t)unit * 256 + lane * 8) = *(float4*)h;
    } else {
        int idx = (blockIdx.x - aBlocks) * blockDim.x + threadIdx.x;
        int lane = idx & 31;
        int unit = idx >> 5;
        int kblk = unit & 63;
        int nblk = unit >> 6;
        int gid = lane >> 2, q = lane & 3;
        int n = nblk * 8 + gid;
        int g = n & 3, hh = n >> 2;
        int k0 = kblk * 32 + 2 * q;
        const float* src;
        if (k0 < 1024) src = Wi + ((size_t)g * 1024 + hh) * 1024 + k0;
        else           src = Wh + ((size_t)g * 1024 + hh) * 1024 + (k0 - 1024);
        float2 v0 = *(const float2*)(src);
        float2 v1 = *(const float2*)(src + 8);
        float2 v2 = *(const float2*)(src + 16);
        float2 v3 = *(const float2*)(src + 24);
        __half2 h[4];
        h[0] = __floats2half2_rn(v0.x, v0.y);
        h[1] = __floats2half2_rn(v1.x, v1.y);
        h[2] = __floats2half2_rn(v2.x, v2.y);
        h[3] = __floats2half2_rn(v3.x, v3.y);
        *(float4*)(g_Wpack + (size_t)unit * 256 + lane * 8) = *(float4*)h;
    }
}

// ---------------- persistent GEMM + fused LSTM epilogue ----------------
// 4 warps, warp tile 64x64; 2 CTAs/SM; persistent over tiles.
// Stage cycle per tile: k0->s2, k1->s0, k2->s1, ... (m(kt)=cycle[kt%3], cycle={2,0,1})
// sg gate buffer = stages 0+1 exactly (64KB, XOR-swizzled), stage 2 stays live for
// the next tile's k0 (issued during the kt31 consume).
__global__ void __launch_bounds__(THREADS, 2)
lstm_mma(const float* __restrict__ old_c, const float* __restrict__ bi,
         float* __restrict__ out, long long out_size, int grid_stride)
{
    extern __shared__ char dsm[];
    __shared__ float4 s_bias4[32];

    const int tid  = threadIdx.x;
    const int lane = tid & 31;
    const int warp = tid >> 5;            // 0..3
    const int wr = warp >> 1;             // 0..1 -> M
    const int wc = warp & 1;              // 0..1 -> N
    const int gid = lane >> 2, q = lane & 3;

    const uint32_t smem = cvta_s(dsm);
    const long long BH = (long long)MDIM * HDIM;
    const bool seg1 = out_size >= 2 * BH;
    const bool seg2 = out_size >= 3 * BH;

    int t  = blockIdx.x;
    int bm = (t >> 5) * BM;
    int bn = (t & 31) * BN;
    size_t aru = (size_t)(bm / 16) * 128;
    size_t bru = (size_t)(bn / 8) * 64;

    if (tid < 32) {
        int hg = (bn >> 2) + tid;
        s_bias4[tid] = make_float4(bi[hg], bi[1024 + hg], bi[2048 + hg], bi[3072 + hg]);
    }

    float acc[4][8][4];

    auto produceA = [&](size_t base, int kt, int st) {
        uint32_t sa = smem + st * STAGE_BYTES;
#pragma unroll
        for (int i = 0; i < 8; i++) {
            int u = warp * 8 + i;              // mblk = u>>2, ks16 = u&3
            const __half* src = g_Apack +
                (base + (size_t)(u >> 2) * 128 + kt * 4 + (u & 3)) * 256 + lane * 8;
            cp_async16(sa + u * 512 + lane * 16, src);
        }
    };
    auto produceB = [&](size_t base, int kt, int st) {
        uint32_t sb = smem + st * STAGE_BYTES + A_BYTES;
#pragma unroll
        for (int i = 0; i < 8; i++) {
            int u = warp * 8 + i;              // nblk = u>>1, ks32 = u&1
            const __half* src = g_Wpack +
                (base + (size_t)(u >> 1) * 64 + kt * 2 + (u & 1)) * 256 + lane * 8;
            cp_async16(sb + u * 512 + lane * 16, src);
        }
    };

    // software-pipelined consume; optionally interleave production of ktile nk
    auto consume = [&](int st, bool doProd, size_t pa, size_t pb, int nk, int pst) {
        const char* sA = dsm + st * STAGE_BYTES;
        const char* sB = sA + A_BYTES;
        uint32_t afr[2][4][4];
        uint32_t bfr[8][4];
#pragma unroll
        for (int mt = 0; mt < 4; mt++)
            *(uint4*)afr[0][mt] = *(const uint4*)(sA + ((wr * 4 + mt) * 4 + 0) * 512 + lane * 16);
#pragma unroll
        for (int nt = 0; nt < 8; nt++)
            *(uint4*)bfr[nt] = *(const uint4*)(sB + ((wc * 8 + nt) * 2 + 0) * 512 + lane * 16);
#pragma unroll
        for (int mt = 0; mt < 4; mt++)
            *(uint4*)afr[1][mt] = *(const uint4*)(sA + ((wr * 4 + mt) * 4 + 1) * 512 + lane * 16);
        // ks16=0
#pragma unroll
        for (int mt = 0; mt < 4; mt++)
#pragma unroll
            for (int nt = 0; nt < 8; nt++)
                mma_f16(acc[mt][nt], afr[0][mt], &bfr[nt][0]);
        if (doProd) produceA(pa, nk, pst);
#pragma unroll
        for (int mt = 0; mt < 4; mt++)
            *(uint4*)afr[0][mt] = *(const uint4*)(sA + ((wr * 4 + mt) * 4 + 2) * 512 + lane * 16);
        // ks16=1
#pragma unroll
        for (int mt = 0; mt < 4; mt++)
#pragma unroll
            for (int nt = 0; nt < 8; nt++)
                mma_f16(acc[mt][nt], afr[1][mt], &bfr[nt][2]);
        if (doProd) produceB(pb, nk, pst);
        // reload bfr <- ks32=1 (WAR safe)
#pragma unroll
        for (int nt = 0; nt < 8; nt++)
            *(uint4*)bfr[nt] = *(const uint4*)(sB + ((wc * 8 + nt) * 2 + 1) * 512 + lane * 16);
#pragma unroll
        for (int mt = 0; mt < 4; mt++)
            *(uint4*)afr[1][mt] = *(const uint4*)(sA + ((wr * 4 + mt) * 4 + 3) * 512 + lane * 16);
        // ks16=2
#pragma unroll
        for (int mt = 0; mt < 4; mt++)
#pragma unroll
            for (int nt = 0; nt < 8; nt++)
                mma_f16(acc[mt][nt], afr[0][mt], &bfr[nt][0]);
        cp_commit();                         // one commit per ktile position (empty ok)
        // ks16=3
#pragma unroll
        for (int mt = 0; mt < 4; mt++)
#pragma unroll
            for (int nt = 0; nt < 8; nt++)
                mma_f16(acc[mt][nt], afr[1][mt], &bfr[nt][2]);
    };

    // prologue: k0 -> stage2, k1 -> stage0
    produceA(aru, 0, 2); produceB(bru, 0, 2); cp_commit();
    produceA(aru, 1, 0); produceB(bru, 1, 0); cp_commit();

    float2* sg2 = (float2*)dsm;

    while (true) {
#pragma unroll
        for (int a = 0; a < 4; a++)
#pragma unroll
            for (int b = 0; b < 8; b++)
#pragma unroll
                for (int c = 0; c < 4; c++) acc[a][b][c] = 0.f;

        int tn = t + grid_stride;
        bool hasNext = tn < NT_TILES;
        int nbm = 0, nbn = 0;
        size_t naru = 0, nbru = 0;
        if (hasNext) {
            nbm = (tn >> 5) * BM;
            nbn = (tn & 31) * BN;
            naru = (size_t)(nbm / 16) * 128;
            nbru = (size_t)(nbn / 8) * 64;
        }

        // mainloop: consumes kt in stages (2,0,1) repeating; produce kt+2 two ahead
#pragma unroll 1
        for (int kt = 0; kt < 30; kt += 3) {
            CP_WAIT(1); __syncthreads();
            consume(2, true, aru, bru, kt + 2, 1);

            CP_WAIT(1); __syncthreads();
            consume(0, true, aru, bru, kt + 3, 2);

            CP_WAIT(1); __syncthreads();
            consume(1, true, aru, bru, kt + 4, 0);
        }
        // kt=30 (stage 2): nothing to produce (commits empty group)
        CP_WAIT(1); __syncthreads();
        consume(2, false, 0, 0, 0, 0);
        // kt=31 (stage 0): produce NEXT tile's k0 -> stage 2 (free since kt30 sync)
        CP_WAIT(1); __syncthreads();
        consume(0, hasNext, naru, nbru, 0, 2);

        // ---- epilogue for tile t (next k0 streams into stage 2 meanwhile) ----
        const int hbase = bn >> 2;
        float ocs[32];
#pragma unroll
        for (int it = 0; it < 32; it++) {
            int idx = it * THREADS + tid;
            int row = idx >> 5;
            int h   = idx & 31;
            ocs[it] = __ldcs(old_c + (size_t)(bm + row) * HDIM + hbase + h);
        }

        __syncthreads();     // all warps done reading stage 0 (kt31) before sg writes

        // Phase A: dump gates to sg (stages 0+1, 64KB exactly, XOR swizzle)
#pragma unroll
        for (int mt = 0; mt < 4; mt++) {
#pragma unroll
            for (int rr = 0; rr < 2; rr++) {
                int row = wr * 64 + mt * 16 + gid + rr * 8;
                int sw = (row & 7) << 1;
#pragma unroll
                for (int nt = 0; nt < 8; nt++) {
                    int h = wc * 16 + nt * 2 + (q >> 1);
                    int j = (2 * h + (q & 1)) ^ sw;
                    sg2[row * 64 + j] =
                        make_float2(acc[mt][nt][rr * 2 + 0], acc[mt][nt][rr * 2 + 1]);
                }
            }
        }
        __syncthreads();

        // Phase B: coalesced cell update + streaming stores
#pragma unroll 4
        for (int it = 0; it < 32; it++) {
            int idx = it * THREADS + tid;
            int row = idx >> 5;
            int h   = idx & 31;
            int j0 = (2 * h) ^ ((row & 7) << 1);
            float4 ga = *(const float4*)(sg2 + row * 64 + j0);
            float4 bb = s_bias4[h];
            size_t gidx = (size_t)(bm + row) * HDIM + hbase + h;
            float iv = sigmoid_fast(ga.x + bb.x);
            float fv = sigmoid_fast(ga.y + bb.y);
            float gv = tanh_fast(ga.z + bb.z);
            float ov = sigmoid_fast(ga.w + bb.w);
            float nc = fmaf(fv, ocs[it], iv * gv);
            float nh = ov * tanh_fast(nc);
            __stcs(out + gidx, nh);
            if (seg1) __stcs(out + BH + gidx, nh);
            if (seg2) __stcs(out + 2 * BH + gidx, nc);
        }

        if (!hasNext) break;

        __syncthreads();     // sg dead; stage 0 reusable
        produceA(naru, 1, 0); produceB(nbru, 1, 0); cp_commit();   // next k1 -> stage 0
        if (tid < 32) {
            int hg = (nbn >> 2) + tid;
            s_bias4[tid] = make_float4(bi[hg], bi[1024 + hg], bi[2048 + hg], bi[3072 + hg]);
        }
        t = tn; bm = nbm; bn = nbn; aru = naru; bru = nbru;
    }
}

extern "C" void kernel_launch(void* const* d_in, const int* in_sizes, int n_in,
                              void* d_out, int out_size) {
    const float* incoming = (const float*)d_in[0];
    const float* old_h    = (const float*)d_in[1];
    const float* old_c    = (const float*)d_in[2];
    const float* Wi       = (const float*)d_in[3];
    const float* bi       = (const float*)d_in[4];
    const float* Wh       = (const float*)d_in[5];
    float* out = (float*)d_out;

    int aBlocks = (MDIM / 16) * (KDIM / 16) * 32 / 256;   // 16384
    int wBlocks = (NDIM / 8) * (KDIM / 32) * 32 / 256;    // 4096
    pack_AW<<<aBlocks + wBlocks, 256>>>(incoming, old_h, Wi, Wh, aBlocks);

    static int nsm = 0;
    if (!nsm) {
        cudaDeviceGetAttribute(&nsm, cudaDevAttrMultiProcessorCount, 0);
        if (nsm <= 0) nsm = 148;
        cudaFuncSetAttribute(lstm_mma, cudaFuncAttributeMaxDynamicSharedMemorySize,
                             STAGES * STAGE_BYTES);
    }
    int grid = 2 * nsm;
    if (grid > NT_TILES) grid = NT_TILES;
    lstm_mma<<<grid, THREADS, STAGES * STAGE_BYTES>>>(old_c, bi, out,
                                                      (long long)out_size, grid);
}

// round 15
// speedup vs baseline: 1.0896x; 1.0896x over previous
#include <cuda_runtime.h>
#include <cuda_fp16.h>
#include <cstdint>
#include <cstddef>

#define MDIM 16384
#define NDIM 4096
#define KDIM 2048
#define HDIM 1024

#define BM 128
#define BN 128
#define BK 64
#define STAGES 3
#define THREADS 128
#define NKT (KDIM / BK)              // 32

#define A_BYTES 16384
#define B_BYTES 16384
#define STAGE_BYTES (A_BYTES + B_BYTES)   // 32768

// Fragment-packed operands (device globals: allowed scratch)
__device__ __half g_Apack[(size_t)MDIM * KDIM];   // 64 MB
__device__ __half g_Wpack[(size_t)NDIM * KDIM];   // 16 MB

// ---------------- helpers ----------------
__device__ __forceinline__ uint32_t cvta_s(const void* p) {
    return (uint32_t)__cvta_generic_to_shared(p);
}
__device__ __forceinline__ void cp_async16(uint32_t s, const void* g) {
    asm volatile("cp.async.cg.shared.global [%0], [%1], 16;\n" :: "r"(s), "l"(g));
}
__device__ __forceinline__ void cp_commit() { asm volatile("cp.async.commit_group;\n" ::: "memory"); }
#define CP_WAIT(n) asm volatile("cp.async.wait_group %0;\n" :: "n"(n) : "memory")

__device__ __forceinline__ void mma_f16(float* d, const uint32_t* a, const uint32_t* b) {
    asm volatile("mma.sync.aligned.m16n8k16.row.col.f32.f16.f16.f32 "
        "{%0,%1,%2,%3}, {%4,%5,%6,%7}, {%8,%9}, {%0,%1,%2,%3};\n"
        : "+f"(d[0]), "+f"(d[1]), "+f"(d[2]), "+f"(d[3])
        : "r"(a[0]), "r"(a[1]), "r"(a[2]), "r"(a[3]), "r"(b[0]), "r"(b[1]));
}
__device__ __forceinline__ float tanh_fast(float x) {
    float r; asm("tanh.approx.f32 %0, %1;\n" : "=f"(r) : "f"(x)); return r;
}
__device__ __forceinline__ float sigmoid_fast(float x) {
    return fmaf(tanh_fast(0.5f * x), 0.5f, 0.5f);
}

// ---------------- merged pack kernel (verified round 7) ----------------
__global__ void pack_AW(const float* __restrict__ inc, const float* __restrict__ oh,
                        const float* __restrict__ Wi, const float* __restrict__ Wh,
                        int aBlocks) {
    if ((int)blockIdx.x < aBlocks) {
        int idx = blockIdx.x * blockDim.x + threadIdx.x;
        int lane = idx & 31;
        int unit = idx >> 5;
        int kblk = unit & 127;
        int mblk = unit >> 7;
        int gid = lane >> 2, q = lane & 3;
        int m0 = mblk * 16 + gid;
        int k0 = kblk * 16 + 2 * q;
        const float* src;
        if (k0 < 1024) src = inc + (size_t)m0 * 1024 + k0;
        else           src = oh  + (size_t)m0 * 1024 + (k0 - 1024);
        float2 v0 = *(const float2*)(src);
        float2 v1 = *(const float2*)(src + 8 * 1024);
        float2 v2 = *(const float2*)(src + 8);
        float2 v3 = *(const float2*)(src + 8 * 1024 + 8);
        __half2 h[4];
        h[0] = __floats2half2_rn(v0.x, v0.y);
        h[1] = __floats2half2_rn(v1.x, v1.y);
        h[2] = __floats2half2_rn(v2.x, v2.y);
        h[3] = __floats2half2_rn(v3.x, v3.y);
        *(float4*)(g_Apack + (size_t)unit * 256 + lane * 8) = *(float4*)h;
    } else {
        int idx = (blockIdx.x - aBlocks) * blockDim.x + threadIdx.x;
        int lane = idx & 31;
        int unit = idx >> 5;
        int kblk = unit & 63;
        int nblk = unit >> 6;
        int gid = lane >> 2, q = lane & 3;
        int n = nblk * 8 + gid;
        int g = n & 3, hh = n >> 2;
        int k0 = kblk * 32 + 2 * q;
        const float* src;
        if (k0 < 1024) src = Wi + ((size_t)g * 1024 + hh) * 1024 + k0;
        else           src = Wh + ((size_t)g * 1024 + hh) * 1024 + (k0 - 1024);
        float2 v0 = *(const float2*)(src);
        float2 v1 = *(const float2*)(src + 8);
        float2 v2 = *(const float2*)(src + 16);
        float2 v3 = *(const float2*)(src + 24);
        __half2 h[4];
        h[0] = __floats2half2_rn(v0.x, v0.y);
        h[1] = __floats2half2_rn(v1.x, v1.y);
        h[2] = __floats2half2_rn(v2.x, v2.y);
        h[3] = __floats2half2_rn(v3.x, v3.y);
        *(float4*)(g_Wpack + (size_t)unit * 256 + lane * 8) = *(float4*)h;
    }
}

// ---------------- main GEMM + fused LSTM epilogue ----------------
// 4 warps, warp tile 64x64, warp grid 2(M) x 2(N); 2 CTAs/SM.
// cp.async production split into 4 chunks spread across the 4 HMMA blocks.
__global__ void __launch_bounds__(THREADS, 2)
lstm_mma(const float* __restrict__ old_c, const float* __restrict__ bi,
         float* __restrict__ out, long long out_size)
{
    extern __shared__ char dsm[];
    __shared__ float4 s_bias4[32];

    const int tid  = threadIdx.x;
    const int lane = tid & 31;
    const int warp = tid >> 5;            // 0..3
    const int wr = warp >> 1;             // 0..1 -> M
    const int wc = warp & 1;              // 0..1 -> N
    const int bm = blockIdx.y * BM;
    const int bn = blockIdx.x * BN;
    const int gid = lane >> 2, q = lane & 3;

    const uint32_t smem = cvta_s(dsm);

    if (tid < 32) {
        int hg = (bn >> 2) + tid;
        s_bias4[tid] = make_float4(bi[hg], bi[1024 + hg], bi[2048 + hg], bi[3072 + hg]);
    }

    float acc[4][8][4];
#pragma unroll
    for (int a = 0; a < 4; a++)
#pragma unroll
        for (int b = 0; b < 8; b++)
#pragma unroll
            for (int c = 0; c < 4; c++) acc[a][b][c] = 0.f;

    const size_t a_row_unit = (size_t)(bm / 16) * 128;
    const size_t b_row_unit = (size_t)(bn / 8) * 64;

    // half-producers: 4 cp.async16 per warp each
    auto produceA_h = [&](int kt, int st, int half) {
        uint32_t sa = smem + st * STAGE_BYTES;
#pragma unroll
        for (int i = 0; i < 4; i++) {
            int u = warp * 8 + half * 4 + i;       // 0..31: mblk = u>>2, ks16 = u&3
            const __half* src = g_Apack +
                (a_row_unit + (size_t)(u >> 2) * 128 + kt * 4 + (u & 3)) * 256 + lane * 8;
            cp_async16(sa + u * 512 + lane * 16, src);
        }
    };
    auto produceB_h = [&](int kt, int st, int half) {
        uint32_t sb = smem + st * STAGE_BYTES + A_BYTES;
#pragma unroll
        for (int i = 0; i < 4; i++) {
            int u = warp * 8 + half * 4 + i;       // 0..31: nblk = u>>1, ks32 = u&1
            const __half* src = g_Wpack +
                (b_row_unit + (size_t)(u >> 1) * 64 + kt * 2 + (u & 1)) * 256 + lane * 8;
            cp_async16(sb + u * 512 + lane * 16, src);
        }
    };

    // software-pipelined consume; production of ktile nk spread over 4 chunks
    auto consume = [&](int st, bool doProd, int nk, int pst) {
        const char* sA = dsm + st * STAGE_BYTES;
        const char* sB = sA + A_BYTES;
        uint32_t afr[2][4][4];
        uint32_t bfr[8][4];
        // prime: afr slot0 <- ks16=0, bfr <- ks32=0
#pragma unroll
        for (int mt = 0; mt < 4; mt++)
            *(uint4*)afr[0][mt] = *(const uint4*)(sA + ((wr * 4 + mt) * 4 + 0) * 512 + lane * 16);
#pragma unroll
        for (int nt = 0; nt < 8; nt++)
            *(uint4*)bfr[nt] = *(const uint4*)(sB + ((wc * 8 + nt) * 2 + 0) * 512 + lane * 16);
        // prefetch afr slot1 <- ks16=1
#pragma unroll
        for (int mt = 0; mt < 4; mt++)
            *(uint4*)afr[1][mt] = *(const uint4*)(sA + ((wr * 4 + mt) * 4 + 1) * 512 + lane * 16);
        // ks16=0
#pragma unroll
        for (int mt = 0; mt < 4; mt++)
#pragma unroll
            for (int nt = 0; nt < 8; nt++)
                mma_f16(acc[mt][nt], afr[0][mt], &bfr[nt][0]);
        if (doProd) produceA_h(nk, pst, 0);       // chunk 1
        // prefetch afr slot0 <- ks16=2
#pragma unroll
        for (int mt = 0; mt < 4; mt++)
            *(uint4*)afr[0][mt] = *(const uint4*)(sA + ((wr * 4 + mt) * 4 + 2) * 512 + lane * 16);
        // ks16=1
#pragma unroll
        for (int mt = 0; mt < 4; mt++)
#pragma unroll
            for (int nt = 0; nt < 8; nt++)
                mma_f16(acc[mt][nt], afr[1][mt], &bfr[nt][2]);
        if (doProd) produceA_h(nk, pst, 1);       // chunk 2
        // reload bfr <- ks32=1 (WAR safe: prior HMMAs already issued)
#pragma unroll
        for (int nt = 0; nt < 8; nt++)
            *(uint4*)bfr[nt] = *(const uint4*)(sB + ((wc * 8 + nt) * 2 + 1) * 512 + lane * 16);
        if (doProd) produceB_h(nk, pst, 0);       // chunk 3
        // prefetch afr slot1 <- ks16=3
#pragma unroll
        for (int mt = 0; mt < 4; mt++)
            *(uint4*)afr[1][mt] = *(const uint4*)(sA + ((wr * 4 + mt) * 4 + 3) * 512 + lane * 16);
        // ks16=2
#pragma unroll
        for (int mt = 0; mt < 4; mt++)
#pragma unroll
            for (int nt = 0; nt < 8; nt++)
                mma_f16(acc[mt][nt], afr[0][mt], &bfr[nt][0]);
        if (doProd) produceB_h(nk, pst, 1);       // chunk 4 (all 16 copies in)
        cp_commit();                               // one commit per ktile position
        // ks16=3
#pragma unroll
        for (int mt = 0; mt < 4; mt++)
#pragma unroll
            for (int nt = 0; nt < 8; nt++)
                mma_f16(acc[mt][nt], afr[1][mt], &bfr[nt][2]);
    };

    // prologue: stages 0,1
    produceA_h(0, 0, 0); produceA_h(0, 0, 1); produceB_h(0, 0, 0); produceB_h(0, 0, 1); cp_commit();
    produceA_h(1, 1, 0); produceA_h(1, 1, 1); produceB_h(1, 1, 0); produceB_h(1, 1, 1); cp_commit();

    // unroll-3 mainloop, round-9-proven ordering: wait -> barrier -> consume(+produce)
#pragma unroll 1
    for (int kt = 0; kt < 30; kt += 3) {
        CP_WAIT(1); __syncthreads();
        consume(0, true, kt + 2, 2);

        CP_WAIT(1); __syncthreads();
        consume(1, true, kt + 3, 0);

        CP_WAIT(1); __syncthreads();
        consume(2, true, kt + 4, 1);
    }
    // tail: kt=30 (stage 0), kt=31 (stage 1); pending g30, g31
    CP_WAIT(1); __syncthreads();
    consume(0, false, 0, 0);
    CP_WAIT(0); __syncthreads();
    consume(1, false, 0, 0);

    // ---- prefetch old_c (coalesced, streaming) while Phase A runs ----
    const int hbase = bn >> 2;
    float ocs[32];
#pragma unroll
    for (int it = 0; it < 32; it++) {
        int idx = it * THREADS + tid;
        int row = idx >> 5;
        int h   = idx & 31;
        ocs[it] = __ldcs(old_c + (size_t)(bm + row) * HDIM + hbase + h);
    }

    __syncthreads();

    // ---- Phase A: dump raw gate pre-activations to smem ----
    float* sg = (float*)dsm;
#pragma unroll
    for (int mt = 0; mt < 4; mt++) {
#pragma unroll
        for (int rr = 0; rr < 2; rr++) {
            int row = wr * 64 + mt * 16 + gid + rr * 8;
#pragma unroll
            for (int nt = 0; nt < 8; nt++) {
                int h = wc * 16 + nt * 2 + (q >> 1);
                *(float2*)(sg + (row * 33 + h) * 4 + (q & 1) * 2) =
                    make_float2(acc[mt][nt][rr * 2 + 0], acc[mt][nt][rr * 2 + 1]);
            }
        }
    }
    __syncthreads();

    // ---- Phase B: coalesced cell update + streaming stores ----
    const long long BH = (long long)MDIM * HDIM;
    const bool seg1 = out_size >= 2 * BH;
    const bool seg2 = out_size >= 3 * BH;

#pragma unroll 4
    for (int it = 0; it < 32; it++) {
        int idx = it * THREADS + tid;
        int row = idx >> 5;
        int h   = idx & 31;
        float4 ga = *(const float4*)(sg + (row * 33 + h) * 4);
        float4 bb = s_bias4[h];
        size_t gidx = (size_t)(bm + row) * HDIM + hbase + h;
        float iv = sigmoid_fast(ga.x + bb.x);
        float fv = sigmoid_fast(ga.y + bb.y);
        float gv = tanh_fast(ga.z + bb.z);
        float ov = sigmoid_fast(ga.w + bb.w);
        float nc = fmaf(fv, ocs[it], iv * gv);
        float nh = ov * tanh_fast(nc);
        __stcs(out + gidx, nh);
        if (seg1) __stcs(out + BH + gidx, nh);
        if (seg2) __stcs(out + 2 * BH + gidx, nc);
    }
}

extern "C" void kernel_launch(void* const* d_in, const int* in_sizes, int n_in,
                              void* d_out, int out_size) {
    const float* incoming = (const float*)d_in[0];
    const float* old_h    = (const float*)d_in[1];
    const float* old_c    = (const float*)d_in[2];
    const float* Wi       = (const float*)d_in[3];
    const float* bi       = (const float*)d_in[4];
    const float* Wh       = (const float*)d_in[5];
    float* out = (float*)d_out;

    int aBlocks = (MDIM / 16) * (KDIM / 16) * 32 / 256;   // 16384
    int wBlocks = (NDIM / 8) * (KDIM / 32) * 32 / 256;    // 4096
    pack_AW<<<aBlocks + wBlocks, 256>>>(incoming, old_h, Wi, Wh, aBlocks);

    static int smem_set = 0;
    if (!smem_set) {
        cudaFuncSetAttribute(lstm_mma, cudaFuncAttributeMaxDynamicSharedMemorySize,
                             STAGES * STAGE_BYTES);
        smem_set = 1;
    }
    dim3 grid(NDIM / BN, MDIM / BM);   // (32, 128)
    lstm_mma<<<grid, THREADS, STAGES * STAGE_BYTES>>>(old_c, bi, out, (long long)out_size);
}

// round 17
// speedup vs baseline: 1.0909x; 1.0012x over previous
#include <cuda_runtime.h>
#include <cuda_fp16.h>
#include <cstdint>
#include <cstddef>

#define MDIM 16384
#define NDIM 4096
#define KDIM 2048
#define HDIM 1024

#define BM 128
#define BN 128
#define BK 64
#define STAGES 3
#define THREADS 128
#define NKT (KDIM / BK)              // 32

#define A_BYTES 16384
#define B_BYTES 16384
#define STAGE_BYTES (A_BYTES + B_BYTES)   // 32768

// Fragment-packed operands (device globals: allowed scratch)
__device__ __half g_Apack[(size_t)MDIM * KDIM];   // 64 MB
__device__ __half g_Wpack[(size_t)NDIM * KDIM];   // 16 MB

// ---------------- helpers ----------------
__device__ __forceinline__ uint32_t cvta_s(const void* p) {
    return (uint32_t)__cvta_generic_to_shared(p);
}
__device__ __forceinline__ void cp_async16(uint32_t s, const void* g) {
    asm volatile("cp.async.cg.shared.global [%0], [%1], 16;\n" :: "r"(s), "l"(g));
}
__device__ __forceinline__ void cp_commit() { asm volatile("cp.async.commit_group;\n" ::: "memory"); }
#define CP_WAIT(n) asm volatile("cp.async.wait_group %0;\n" :: "n"(n) : "memory")

// 32-bit shared-window vector load (keeps addressing in one IADD; order pinned)
__device__ __forceinline__ void lds128(uint32_t* r, uint32_t addr) {
    asm volatile("ld.shared.v4.b32 {%0,%1,%2,%3}, [%4];"
        : "=r"(r[0]), "=r"(r[1]), "=r"(r[2]), "=r"(r[3]) : "r"(addr));
}

__device__ __forceinline__ void mma_f16(float* d, const uint32_t* a, const uint32_t* b) {
    asm volatile("mma.sync.aligned.m16n8k16.row.col.f32.f16.f16.f32 "
        "{%0,%1,%2,%3}, {%4,%5,%6,%7}, {%8,%9}, {%0,%1,%2,%3};\n"
        : "+f"(d[0]), "+f"(d[1]), "+f"(d[2]), "+f"(d[3])
        : "r"(a[0]), "r"(a[1]), "r"(a[2]), "r"(a[3]), "r"(b[0]), "r"(b[1]));
}
__device__ __forceinline__ float tanh_fast(float x) {
    float r; asm("tanh.approx.f32 %0, %1;\n" : "=f"(r) : "f"(x)); return r;
}
__device__ __forceinline__ float sigmoid_fast(float x) {
    return fmaf(tanh_fast(0.5f * x), 0.5f, 0.5f);
}

// ---------------- merged pack kernel (verified round 7) ----------------
__global__ void pack_AW(const float* __restrict__ inc, const float* __restrict__ oh,
                        const float* __restrict__ Wi, const float* __restrict__ Wh,
                        int aBlocks) {
    if ((int)blockIdx.x < aBlocks) {
        int idx = blockIdx.x * blockDim.x + threadIdx.x;
        int lane = idx & 31;
        int unit = idx >> 5;
        int kblk = unit & 127;
        int mblk = unit >> 7;
        int gid = lane >> 2, q = lane & 3;
        int m0 = mblk * 16 + gid;
        int k0 = kblk * 16 + 2 * q;
        const float* src;
        if (k0 < 1024) src = inc + (size_t)m0 * 1024 + k0;
        else           src = oh  + (size_t)m0 * 1024 + (k0 - 1024);
        float2 v0 = *(const float2*)(src);
        float2 v1 = *(const float2*)(src + 8 * 1024);
        float2 v2 = *(const float2*)(src + 8);
        float2 v3 = *(const float2*)(src + 8 * 1024 + 8);
        __half2 h[4];
        h[0] = __floats2half2_rn(v0.x, v0.y);
        h[1] = __floats2half2_rn(v1.x, v1.y);
        h[2] = __floats2half2_rn(v2.x, v2.y);
        h[3] = __floats2half2_rn(v3.x, v3.y);
        *(float4*)(g_Apack + (size_t)unit * 256 + lane * 8) = *(float4*)h;
    } else {
        int idx = (blockIdx.x - aBlocks) * blockDim.x + threadIdx.x;
        int lane = idx & 31;
        int unit = idx >> 5;
        int kblk = unit & 63;
        int nblk = unit >> 6;
        int gid = lane >> 2, q = lane & 3;
        int n = nblk * 8 + gid;
        int g = n & 3, hh = n >> 2;
        int k0 = kblk * 32 + 2 * q;
        const float* src;
        if (k0 < 1024) src = Wi + ((size_t)g * 1024 + hh) * 1024 + k0;
        else           src = Wh + ((size_t)g * 1024 + hh) * 1024 + (k0 - 1024);
        float2 v0 = *(const float2*)(src);
        float2 v1 = *(const float2*)(src + 8);
        float2 v2 = *(const float2*)(src + 16);
        float2 v3 = *(const float2*)(src + 24);
        __half2 h[4];
        h[0] = __floats2half2_rn(v0.x, v0.y);
        h[1] = __floats2half2_rn(v1.x, v1.y);
        h[2] = __floats2half2_rn(v2.x, v2.y);
        h[3] = __floats2half2_rn(v3.x, v3.y);
        *(float4*)(g_Wpack + (size_t)unit * 256 + lane * 8) = *(float4*)h;
    }
}

// ---------------- main GEMM + fused LSTM epilogue ----------------
// 4 warps, warp tile 64x64, warp grid 2(M) x 2(N); 2 CTAs/SM.
// All mainloop smem addressing is 32-bit shared-window arithmetic.
__global__ void __launch_bounds__(THREADS, 2)
lstm_mma(const float* __restrict__ old_c, const float* __restrict__ bi,
         float* __restrict__ out, long long out_size)
{
    extern __shared__ char dsm[];
    __shared__ float4 s_bias4[32];

    const int tid  = threadIdx.x;
    const int lane = tid & 31;
    const int warp = tid >> 5;            // 0..3
    const int wr = warp >> 1;             // 0..1 -> M
    const int wc = warp & 1;              // 0..1 -> N
    const int bm = blockIdx.y * BM;
    const int bn = blockIdx.x * BN;
    const int gid = lane >> 2, q = lane & 3;

    const uint32_t smem = cvta_s(dsm);
    // per-thread fragment-read bases (32-bit, loop-invariant)
    const uint32_t abase = smem + lane * 16 + (wr * 4) * 4 * 512;
    const uint32_t bbase = smem + A_BYTES + lane * 16 + (wc * 8) * 2 * 512;
    // per-thread producer store bases
    const uint32_t pstA = smem + (warp * 8) * 512 + lane * 16;
    const uint32_t pstB = smem + A_BYTES + (warp * 8) * 512 + lane * 16;

    if (tid < 32) {
        int hg = (bn >> 2) + tid;
        s_bias4[tid] = make_float4(bi[hg], bi[1024 + hg], bi[2048 + hg], bi[3072 + hg]);
    }

    float acc[4][8][4];
#pragma unroll
    for (int a = 0; a < 4; a++)
#pragma unroll
        for (int b = 0; b < 8; b++)
#pragma unroll
            for (int c = 0; c < 4; c++) acc[a][b][c] = 0.f;

    const size_t a_row_unit = (size_t)(bm / 16) * 128;
    const size_t b_row_unit = (size_t)(bn / 8) * 64;

    // half-producers: 4 cp.async16 per warp each
    auto produceA_h = [&](int kt, int st, int half) {
        uint32_t sa = pstA + st * STAGE_BYTES + half * 4 * 512;
#pragma unroll
        for (int i = 0; i < 4; i++) {
            int u = warp * 8 + half * 4 + i;       // mblk = u>>2, ks16 = u&3
            const __half* src = g_Apack +
                (a_row_unit + (size_t)(u >> 2) * 128 + kt * 4 + (u & 3)) * 256 + lane * 8;
            cp_async16(sa + i * 512, src);
        }
    };
    auto produceB_h = [&](int kt, int st, int half) {
        uint32_t sb = pstB + st * STAGE_BYTES + half * 4 * 512;
#pragma unroll
        for (int i = 0; i < 4; i++) {
            int u = warp * 8 + half * 4 + i;       // nblk = u>>1, ks32 = u&1
            const __half* src = g_Wpack +
                (b_row_unit + (size_t)(u >> 1) * 64 + kt * 2 + (u & 1)) * 256 + lane * 8;
            cp_async16(sb + i * 512, src);
        }
    };

    // software-pipelined consume; production of ktile nk spread over 4 chunks
    auto consume = [&](int st, bool doProd, int nk, int pst) {
        const uint32_t sA = abase + st * STAGE_BYTES;   // + mt*4*512 + ks16*512
        const uint32_t sB = bbase + st * STAGE_BYTES;   // + nt*2*512 + ks32*512
        uint32_t afr[2][4][4];
        uint32_t bfr[8][4];
        // prime: afr slot0 <- ks16=0, bfr <- ks32=0
#pragma unroll
        for (int mt = 0; mt < 4; mt++) lds128(afr[0][mt], sA + mt * 2048);
#pragma unroll
        for (int nt = 0; nt < 8; nt++) lds128(bfr[nt], sB + nt * 1024);
        // prefetch afr slot1 <- ks16=1
#pragma unroll
        for (int mt = 0; mt < 4; mt++) lds128(afr[1][mt], sA + mt * 2048 + 512);
        // ks16=0
#pragma unroll
        for (int mt = 0; mt < 4; mt++)
#pragma unroll
            for (int nt = 0; nt < 8; nt++)
                mma_f16(acc[mt][nt], afr[0][mt], &bfr[nt][0]);
        if (doProd) produceA_h(nk, pst, 0);       // chunk 1
        // prefetch afr slot0 <- ks16=2
#pragma unroll
        for (int mt = 0; mt < 4; mt++) lds128(afr[0][mt], sA + mt * 2048 + 1024);
        // ks16=1
#pragma unroll
        for (int mt = 0; mt < 4; mt++)
#pragma unroll
            for (int nt = 0; nt < 8; nt++)
                mma_f16(acc[mt][nt], afr[1][mt], &bfr[nt][2]);
        if (doProd) produceA_h(nk, pst, 1);       // chunk 2
        // reload bfr <- ks32=1 (WAR safe: prior HMMAs already issued)
#pragma unroll
        for (int nt = 0; nt < 8; nt++) lds128(bfr[nt], sB + nt * 1024 + 512);
        if (doProd) produceB_h(nk, pst, 0);       // chunk 3
        // prefetch afr slot1 <- ks16=3
#pragma unroll
        for (int mt = 0; mt < 4; mt++) lds128(afr[1][mt], sA + mt * 2048 + 1536);
        // ks16=2
#pragma unroll
        for (int mt = 0; mt < 4; mt++)
#pragma unroll
            for (int nt = 0; nt < 8; nt++)
                mma_f16(acc[mt][nt], afr[0][mt], &bfr[nt][0]);
        if (doProd) produceB_h(nk, pst, 1);       // chunk 4 (all 16 copies in)
        cp_commit();                               // one commit per ktile position
        // ks16=3
#pragma unroll
        for (int mt = 0; mt < 4; mt++)
#pragma unroll
            for (int nt = 0; nt < 8; nt++)
                mma_f16(acc[mt][nt], afr[1][mt], &bfr[nt][2]);
    };

    // prologue: stages 0,1
    produceA_h(0, 0, 0); produceA_h(0, 0, 1); produceB_h(0, 0, 0); produceB_h(0, 0, 1); cp_commit();
    produceA_h(1, 1, 0); produceA_h(1, 1, 1); produceB_h(1, 1, 0); produceB_h(1, 1, 1); cp_commit();

    // unroll-3 mainloop, round-9-proven ordering: wait -> barrier -> consume(+produce)
#pragma unroll 1
    for (int kt = 0; kt < 30; kt += 3) {
        CP_WAIT(1); __syncthreads();
        consume(0, true, kt + 2, 2);

        CP_WAIT(1); __syncthreads();
        consume(1, true, kt + 3, 0);

        CP_WAIT(1); __syncthreads();
        consume(2, true, kt + 4, 1);
    }
    // tail: kt=30 (stage 0), kt=31 (stage 1); pending g30, g31
    CP_WAIT(1); __syncthreads();
    consume(0, false, 0, 0);
    CP_WAIT(0); __syncthreads();
    consume(1, false, 0, 0);

    // ---- prefetch old_c (coalesced, streaming) while Phase A runs ----
    const int hbase = bn >> 2;
    float ocs[32];
#pragma unroll
    for (int it = 0; it < 32; it++) {
        int idx = it * THREADS + tid;
        int row = idx >> 5;
        int h   = idx & 31;
        ocs[it] = __ldcs(old_c + (size_t)(bm + row) * HDIM + hbase + h);
    }

    __syncthreads();

    // ---- Phase A: dump raw gate pre-activations to smem ----
    float* sg = (float*)dsm;
#pragma unroll
    for (int mt = 0; mt < 4; mt++) {
#pragma unroll
        for (int rr = 0; rr < 2; rr++) {
            int row = wr * 64 + mt * 16 + gid + rr * 8;
#pragma unroll
            for (int nt = 0; nt < 8; nt++) {
                int h = wc * 16 + nt * 2 + (q >> 1);
                *(float2*)(sg + (row * 33 + h) * 4 + (q & 1) * 2) =
                    make_float2(acc[mt][nt][rr * 2 + 0], acc[mt][nt][rr * 2 + 1]);
            }
        }
    }
    __syncthreads();

    // ---- Phase B: coalesced cell update + streaming stores ----
    const long long BH = (long long)MDIM * HDIM;
    const bool seg1 = out_size >= 2 * BH;
    const bool seg2 = out_size >= 3 * BH;

#pragma unroll 4
    for (int it = 0; it < 32; it++) {
        int idx = it * THREADS + tid;
        int row = idx >> 5;
        int h   = idx & 31;
        float4 ga = *(const float4*)(sg + (row * 33 + h) * 4);
        float4 bb = s_bias4[h];
        size_t gidx = (size_t)(bm + row) * HDIM + hbase + h;
        float iv = sigmoid_fast(ga.x + bb.x);
        float fv = sigmoid_fast(ga.y + bb.y);
        float gv = tanh_fast(ga.z + bb.z);
        float ov = sigmoid_fast(ga.w + bb.w);
        float nc = fmaf(fv, ocs[it], iv * gv);
        float nh = ov * tanh_fast(nc);
        __stcs(out + gidx, nh);
        if (seg1) __stcs(out + BH + gidx, nh);
        if (seg2) __stcs(out + 2 * BH + gidx, nc);
    }
}

extern "C" void kernel_launch(void* const* d_in, const int* in_sizes, int n_in,
                              void* d_out, int out_size) {
    const float* incoming = (const float*)d_in[0];
    const float* old_h    = (const float*)d_in[1];
    const float* old_c    = (const float*)d_in[2];
    const float* Wi       = (const float*)d_in[3];
    const float* bi       = (const float*)d_in[4];
    const float* Wh       = (const float*)d_in[5];
    float* out = (float*)d_out;

    int aBlocks = (MDIM / 16) * (KDIM / 16) * 32 / 256;   // 16384
    int wBlocks = (NDIM / 8) * (KDIM / 32) * 32 / 256;    // 4096
    pack_AW<<<aBlocks + wBlocks, 256>>>(incoming, old_h, Wi, Wh, aBlocks);

    static int smem_set = 0;
    if (!smem_set) {
        cudaFuncSetAttribute(lstm_mma, cudaFuncAttributeMaxDynamicSharedMemorySize,
                             STAGES * STAGE_BYTES);
        smem_set = 1;
    }
    dim3 grid(NDIM / BN, MDIM / BM);   // (32, 128)
    lstm_mma<<<grid, THREADS, STAGES * STAGE_BYTES>>>(old_c, bi, out, (long long)out_size);
}